// round 9
// baseline (speedup 1.0000x reference)
#include <cuda_runtime.h>
#include <math.h>

#define TT 4096
#define BB 32
#define NH 100
#define NM 65

// ---- scratch (__device__ globals: allocations forbidden) ----
__device__ __align__(16) float g_tfac[TT*NH];
__device__ __align__(16) float g_nfac[TT*NM];
__device__ __align__(16) float g_hmid[(size_t)BB*TT*NH];  // 52.4MB
__device__ __align__(16) float g_hmean[TT*NH];
__device__ float g_cmean[TT];
__device__ float g_sreso[TT];

__device__ __forceinline__ float wmax(float v){
  #pragma unroll
  for (int d=16; d; d>>=1) v = fmaxf(v, __shfl_xor_sync(0xffffffffu, v, d));
  return v;
}
__device__ __forceinline__ float wsum(float v){
  #pragma unroll
  for (int d=16; d; d>>=1) v += __shfl_xor_sync(0xffffffffu, v, d);
  return v;
}

// ---- K0: per-(t,j) sinusoidal factors, flat launch ------------------------
__global__ void k_factors(){
  int idx = blockIdx.x*blockDim.x + threadIdx.x;
  const int TOT = TT*(NH+NM);
  if (idx >= TOT) return;
  int t = idx / (NH+NM);
  int j = idx - t*(NH+NM);
  const double INC  = (double)(float)1.0053096491487339;   // f32(2pi*40*64/16000)
  const double WRAP = (double)(float)6.283185307179586;    // f32(2pi)
  float phase = (float)fmod((double)(t+1)*INC, WRAP);
  if (j < NH) {
    float off = (float)((double)j * (4.71238898038469/99.0));
    g_tfac[t*NH+j] = 1.0f + 0.225f*sinf(phase + off);
  } else {
    int m = j - NH;
    float rb = (float)m * 7.853981633974483f;
    g_nfac[t*NM+m] = 1.0f + 0.6f*sinf(rb + phase);
  }
}

// ---- K1: stats + h_mid store (blocks [0,TT)), noise stream (blocks >= TT) -
__global__ __launch_bounds__(512) void k_stats(const float* __restrict__ harm,
                                               const float4* __restrict__ nin,
                                               float4* __restrict__ outn){
  int bid = blockIdx.x;
  if (bid >= TT){
    const int NVN = BB*TT*NM/4;
    int idx = (bid - TT)*512 + threadIdx.x;
    int stride = (gridDim.x - TT)*512;
    for (int j = idx; j < NVN; j += stride){
      int fi = j % (TT*NM/4);
      float4 v = nin[j];
      float4 f = reinterpret_cast<const float4*>(g_nfac)[fi];
      v.x *= f.x; v.y *= f.y; v.z *= f.z; v.w *= f.w;
      outn[j] = v;
    }
    return;
  }
  int t = bid;
  int warp = threadIdx.x>>5, lane = threadIdx.x&31;     // 16 warps x 2 rows
  __shared__ float4 s_tfac[25];
  __shared__ float  s_hsum[NH];
  __shared__ float  s_csum;
  if (threadIdx.x < 25) s_tfac[threadIdx.x] =
      reinterpret_cast<const float4*>(g_tfac + t*NH)[threadIdx.x];
  if (threadIdx.x < NH) s_hsum[threadIdx.x] = 0.f;
  if (threadIdx.x == 0) s_csum = 0.f;
  __syncthreads();
  bool act = lane < 25;
  float4 f = act ? s_tfac[lane] : make_float4(0.f,0.f,0.f,0.f);
  float4 acc = make_float4(0.f,0.f,0.f,0.f);
  float cacc = 0.f;
  float k0 = (float)(lane*4);
  #pragma unroll
  for (int r=0;r<2;++r){
    int b = warp + r*16;
    size_t rowoff = ((size_t)b*TT + t)*NH;
    float4 x = act ? reinterpret_cast<const float4*>(harm + rowoff)[lane]
                   : make_float4(0.f,0.f,0.f,0.f);
    // single max tree: max(sharp) == max_orig^3.4 (monotone), with ref's clamp
    float mo = fmaxf(fmaxf(x.x,x.y), fmaxf(x.z,x.w));
    mo = fmaxf(wmax(mo), 1e-6f);
    float ms = fmaxf(__powf(mo, 3.4f), 1e-6f);
    float ratio = mo/ms;
    float4 s;
    s.x = __powf(fmaxf(x.x,1e-6f), 3.4f);
    s.y = __powf(fmaxf(x.y,1e-6f), 3.4f);
    s.z = __powf(fmaxf(x.z,1e-6f), 3.4f);
    s.w = __powf(fmaxf(x.w,1e-6f), 3.4f);
    float4 h;
    h.x = s.x*ratio*f.x; h.y = s.y*ratio*f.y;
    h.z = s.z*ratio*f.z; h.w = s.w*ratio*f.w;
    if (!act){ h.x=h.y=h.z=h.w=0.f; }
    float num = h.x*k0 + h.y*(k0+1.f) + h.z*(k0+2.f) + h.w*(k0+3.f);
    float den = h.x+h.y+h.z+h.w;
    num = wsum(num); den = wsum(den);
    if (lane==0) cacc += num / fmaxf(den, 1e-6f);
    if (act) reinterpret_cast<float4*>(g_hmid + rowoff)[lane] = h;
    acc.x+=h.x; acc.y+=h.y; acc.z+=h.z; acc.w+=h.w;
  }
  if (act){
    atomicAdd(&s_hsum[lane*4+0], acc.x);
    atomicAdd(&s_hsum[lane*4+1], acc.y);
    atomicAdd(&s_hsum[lane*4+2], acc.z);
    atomicAdd(&s_hsum[lane*4+3], acc.w);
  }
  if (lane==0) atomicAdd(&s_csum, cacc);
  __syncthreads();
  if (threadIdx.x < NH) g_hmean[t*NH+threadIdx.x] = s_hsum[threadIdx.x] * (1.f/32.f);
  if (threadIdx.x == 0) g_cmean[t] = s_csum * (1.f/32.f);
}

// ---- K2: fb affine scan + clock prefix sum (256 thr x 16 elems, double) ---
__global__ void k_scan(){
  __shared__ double s_clk[TT];
  __shared__ double s_wa[8], s_wb[8], s_ws[8];
  int tid = threadIdx.x;
  int lane = tid & 31, warp = tid >> 5;
  int base = tid * 16;
  const double RATE_K = 0.725 * 6.283185307179586 * 0.004;
  double v = 0.0;
  #pragma unroll
  for (int j=0;j<16;++j){
    double u = 0.1*(((double)g_cmean[base+j] - 30.0)/40.0);
    v = 0.9*v + u;
  }
  double a = 0.18530201888518416;  // 0.9^16
  double b = v;
  #pragma unroll
  for (int d=1; d<32; d<<=1){
    double pa = __shfl_up_sync(0xffffffffu, a, d);
    double pb = __shfl_up_sync(0xffffffffu, b, d);
    if (lane >= d){ b = a*pb + b; a = a*pa; }
  }
  if (lane == 31){ s_wa[warp]=a; s_wb[warp]=b; }
  __syncthreads();
  double wpre = 0.0;
  for (int w=0; w<warp; ++w) wpre = s_wa[w]*wpre + s_wb[w];
  double ae = __shfl_up_sync(0xffffffffu, a, 1);
  double be = __shfl_up_sync(0xffffffffu, b, 1);
  double fb = (lane==0) ? wpre : (ae*wpre + be);
  double csum = 0.0;
  #pragma unroll
  for (int j=0;j<16;++j){
    double u = 0.1*(((double)g_cmean[base+j] - 30.0)/40.0);
    fb = 0.9*fb + u;
    csum += RATE_K * (1.0 + 0.4*fb);
    s_clk[base+j] = csum;
  }
  double S = csum, ss = S;
  #pragma unroll
  for (int d=1; d<32; d<<=1){
    double p = __shfl_up_sync(0xffffffffu, ss, d);
    if (lane >= d) ss += p;
  }
  if (lane == 31) s_ws[warp] = ss;
  __syncthreads();
  double off = 0.0;
  for (int w=0; w<warp; ++w) off += s_ws[w];
  double excl = off + ss - S;
  #pragma unroll
  for (int j=0;j<16;++j){
    double c = fmod(excl + s_clk[base+j], 6.283185307179586);
    g_sreso[base+j] = 0.4f * sinf((float)c);
  }
}

// ---- K3: fused epilogue — one block per t, a/c computed in-block ----------
__global__ __launch_bounds__(256) void k_out(float4* __restrict__ outh){
  int t = blockIdx.x;
  __shared__ float4 s_a[25], s_c[25];
  int tid = threadIdx.x;
  if (tid < 25){
    float sr = g_sreso[t];
    int k4 = tid*4;
    float4 rel;
    rel.x = (float)k4/99.0f*2.0f - 1.0f;
    rel.y = (float)(k4+1)/99.0f*2.0f - 1.0f;
    rel.z = (float)(k4+2)/99.0f*2.0f - 1.0f;
    rel.w = (float)(k4+3)/99.0f*2.0f - 1.0f;
    float scale = (t==0) ? 1.0f : 0.6f;
    float4 a;
    a.x = scale*(1.0f + sr*rel.x); a.y = scale*(1.0f + sr*rel.y);
    a.z = scale*(1.0f + sr*rel.z); a.w = scale*(1.0f + sr*rel.w);
    float4 c = make_float4(0.f,0.f,0.f,0.f);
    if (t >= 149){
      float srp = g_sreso[t-149];
      float4 hm = reinterpret_cast<const float4*>(g_hmean)[(t-149)*25 + tid];
      c.x = 0.4f*(1.0f + srp*rel.x)*hm.x;
      c.y = 0.4f*(1.0f + srp*rel.y)*hm.y;
      c.z = 0.4f*(1.0f + srp*rel.z)*hm.z;
      c.w = 0.4f*(1.0f + srp*rel.w)*hm.w;
    }
    s_a[tid] = a; s_c[tid] = c;
  }
  __syncthreads();
  // 32 rows x 25 float4 = 800 float4 per t
  for (int q = tid; q < 800; q += 256){
    int row = q / 25;
    int kq  = q - row*25;
    size_t idx = ((size_t)row*TT + t)*25 + kq;
    float4 v = reinterpret_cast<const float4*>(g_hmid)[idx];
    float4 a = s_a[kq], c = s_c[kq];
    float4 o;
    o.x = fmaf(a.x, v.x, c.x); o.y = fmaf(a.y, v.y, c.y);
    o.z = fmaf(a.z, v.z, c.z); o.w = fmaf(a.w, v.w, c.w);
    outh[idx] = o;
  }
}

extern "C" void kernel_launch(void* const* d_in, const int* in_sizes, int n_in,
                              void* d_out, int out_size){
  const float* harm  = (const float*)d_in[0];
  const float* noise = (const float*)d_in[1];
  float* outh = (float*)d_out;
  float* outn = outh + (size_t)BB*TT*NH;
  k_factors<<<(TT*(NH+NM)+255)/256, 256>>>();
  k_stats  <<<TT + 2048, 512>>>(harm, (const float4*)noise, (float4*)outn);
  k_scan   <<<1, 256>>>();
  k_out    <<<TT, 256>>>((float4*)outh);
}

// round 10
// speedup vs baseline: 1.1806x; 1.1806x over previous
#include <cuda_runtime.h>
#include <cuda_fp16.h>
#include <math.h>

#define TT 4096
#define BB 32
#define NH 100
#define NM 65

// ---- scratch (__device__ globals: allocations forbidden) ----
__device__ __align__(16) float  g_nfac[TT*NM];
__device__ __align__(16) __half g_hmid[(size_t)BB*TT*NH];   // 26.2MB fp16
__device__ __align__(16) float  g_hmean[TT*NH];
__device__ float g_cmean[TT];
__device__ float g_sreso[TT];

__device__ __forceinline__ float wmax(float v){
  #pragma unroll
  for (int d=16; d; d>>=1) v = fmaxf(v, __shfl_xor_sync(0xffffffffu, v, d));
  return v;
}
__device__ __forceinline__ float wsum(float v){
  #pragma unroll
  for (int d=16; d; d>>=1) v += __shfl_xor_sync(0xffffffffu, v, d);
  return v;
}

// ---- K1: per-t block: factors in-block, stats, fp16 h_mid store -----------
__global__ __launch_bounds__(512) void k_stats(const float* __restrict__ harm){
  int t = blockIdx.x;
  int warp = threadIdx.x>>5, lane = threadIdx.x&31;   // 16 warps x 2 rows
  __shared__ float s_tfac[NH];
  __shared__ float s_hsum[NH];
  __shared__ float s_csum;
  int tid = threadIdx.x;
  if (tid < NH+NM){
    // f32 phase recurrence tracked by double closed form (~1e-5 rad over 4096)
    const double INC  = (double)(float)1.0053096491487339;  // f32(2pi*40*64/16000)
    const double WRAP = (double)(float)6.283185307179586;   // f32(2pi)
    float phase = (float)fmod((double)(t+1)*INC, WRAP);
    if (tid < NH){
      float off = (float)((double)tid * (4.71238898038469/99.0));
      s_tfac[tid] = 1.0f + 0.225f*sinf(phase + off);
    } else {
      int m = tid - NH;
      float rb = (float)m * 7.853981633974483f;             // arange*2.5pi (f32)
      g_nfac[t*NM+m] = 1.0f + 0.6f*sinf(rb + phase);
    }
  }
  if (tid < NH) s_hsum[tid] = 0.f;
  if (tid == 0) s_csum = 0.f;
  __syncthreads();
  bool act = lane < 25;
  float4 f = act ? reinterpret_cast<const float4*>(s_tfac)[lane]
                 : make_float4(0.f,0.f,0.f,0.f);
  float4 acc = make_float4(0.f,0.f,0.f,0.f);
  float cacc = 0.f;
  float k0 = (float)(lane*4);
  #pragma unroll
  for (int r=0;r<2;++r){
    int b = warp + r*16;
    size_t rowoff = ((size_t)b*TT + t)*NH;
    float4 x = act ? reinterpret_cast<const float4*>(harm + rowoff)[lane]
                   : make_float4(0.f,0.f,0.f,0.f);
    // single max tree: max(sharp) == max_orig^3.4 (monotone), ref clamps kept
    float mo = fmaxf(fmaxf(x.x,x.y), fmaxf(x.z,x.w));
    mo = fmaxf(wmax(mo), 1e-6f);
    float ms = fmaxf(__powf(mo, 3.4f), 1e-6f);
    float ratio = mo/ms;
    float4 s;
    s.x = __powf(fmaxf(x.x,1e-6f), 3.4f);
    s.y = __powf(fmaxf(x.y,1e-6f), 3.4f);
    s.z = __powf(fmaxf(x.z,1e-6f), 3.4f);
    s.w = __powf(fmaxf(x.w,1e-6f), 3.4f);
    float4 h;
    h.x = s.x*ratio*f.x; h.y = s.y*ratio*f.y;
    h.z = s.z*ratio*f.z; h.w = s.w*ratio*f.w;
    if (!act){ h.x=h.y=h.z=h.w=0.f; }
    float num = h.x*k0 + h.y*(k0+1.f) + h.z*(k0+2.f) + h.w*(k0+3.f);
    float den = h.x+h.y+h.z+h.w;
    num = wsum(num); den = wsum(den);
    if (lane==0) cacc += num / fmaxf(den, 1e-6f);
    if (act){
      __half2 p0 = __floats2half2_rn(h.x, h.y);
      __half2 p1 = __floats2half2_rn(h.z, h.w);
      uint2 pk;
      pk.x = *reinterpret_cast<unsigned int*>(&p0);
      pk.y = *reinterpret_cast<unsigned int*>(&p1);
      reinterpret_cast<uint2*>(g_hmid + rowoff)[lane] = pk;
    }
    acc.x+=h.x; acc.y+=h.y; acc.z+=h.z; acc.w+=h.w;
  }
  if (act){
    atomicAdd(&s_hsum[lane*4+0], acc.x);
    atomicAdd(&s_hsum[lane*4+1], acc.y);
    atomicAdd(&s_hsum[lane*4+2], acc.z);
    atomicAdd(&s_hsum[lane*4+3], acc.w);
  }
  if (lane==0) atomicAdd(&s_csum, cacc);
  __syncthreads();
  if (tid < NH) g_hmean[t*NH+tid] = s_hsum[tid] * (1.f/32.f);
  if (tid == 0) g_cmean[t] = s_csum * (1.f/32.f);
}

// ---- K2: fb affine scan + clock prefix sum (256 thr x 16 elems, double) ---
__global__ void k_scan(){
  __shared__ double s_clk[TT];
  __shared__ double s_wa[8], s_wb[8], s_ws[8];
  int tid = threadIdx.x;
  int lane = tid & 31, warp = tid >> 5;
  int base = tid * 16;
  const double RATE_K = 0.725 * 6.283185307179586 * 0.004;
  double v = 0.0;
  #pragma unroll
  for (int j=0;j<16;++j){
    double u = 0.1*(((double)g_cmean[base+j] - 30.0)/40.0);
    v = 0.9*v + u;
  }
  double a = 0.18530201888518416;  // 0.9^16
  double b = v;
  #pragma unroll
  for (int d=1; d<32; d<<=1){
    double pa = __shfl_up_sync(0xffffffffu, a, d);
    double pb = __shfl_up_sync(0xffffffffu, b, d);
    if (lane >= d){ b = a*pb + b; a = a*pa; }
  }
  if (lane == 31){ s_wa[warp]=a; s_wb[warp]=b; }
  __syncthreads();
  double wpre = 0.0;
  for (int w=0; w<warp; ++w) wpre = s_wa[w]*wpre + s_wb[w];
  double ae = __shfl_up_sync(0xffffffffu, a, 1);
  double be = __shfl_up_sync(0xffffffffu, b, 1);
  double fb = (lane==0) ? wpre : (ae*wpre + be);
  double csum = 0.0;
  #pragma unroll
  for (int j=0;j<16;++j){
    double u = 0.1*(((double)g_cmean[base+j] - 30.0)/40.0);
    fb = 0.9*fb + u;
    csum += RATE_K * (1.0 + 0.4*fb);
    s_clk[base+j] = csum;
  }
  double S = csum, ss = S;
  #pragma unroll
  for (int d=1; d<32; d<<=1){
    double p = __shfl_up_sync(0xffffffffu, ss, d);
    if (lane >= d) ss += p;
  }
  if (lane == 31) s_ws[warp] = ss;
  __syncthreads();
  double off = 0.0;
  for (int w=0; w<warp; ++w) off += s_ws[w];
  double excl = off + ss - S;
  #pragma unroll
  for (int j=0;j<16;++j){
    double c = fmod(excl + s_clk[base+j], 6.283185307179586);
    g_sreso[base+j] = 0.4f * sinf((float)c);
  }
}

// ---- K3: h epilogue (blocks [0,TT)) + noise stream (blocks >= TT) ---------
__global__ __launch_bounds__(256) void k_out(const float4* __restrict__ nin,
                                             float4* __restrict__ outh,
                                             float4* __restrict__ outn){
  int bid = blockIdx.x;
  int tid = threadIdx.x;
  if (bid >= TT){
    const int NVN = BB*TT*NM/4;
    int idx = (bid - TT)*256 + tid;
    int stride = (gridDim.x - TT)*256;
    for (int j = idx; j < NVN; j += stride){
      int fi = j % (TT*NM/4);
      float4 v = nin[j];
      float4 f = reinterpret_cast<const float4*>(g_nfac)[fi];
      v.x *= f.x; v.y *= f.y; v.z *= f.z; v.w *= f.w;
      outn[j] = v;
    }
    return;
  }
  int t = bid;
  __shared__ float4 s_a[25], s_c[25];
  if (tid < 25){
    float sr = g_sreso[t];
    int k4 = tid*4;
    float4 rel;
    rel.x = (float)k4/99.0f*2.0f - 1.0f;
    rel.y = (float)(k4+1)/99.0f*2.0f - 1.0f;
    rel.z = (float)(k4+2)/99.0f*2.0f - 1.0f;
    rel.w = (float)(k4+3)/99.0f*2.0f - 1.0f;
    float scale = (t==0) ? 1.0f : 0.6f;
    float4 a;
    a.x = scale*(1.0f + sr*rel.x); a.y = scale*(1.0f + sr*rel.y);
    a.z = scale*(1.0f + sr*rel.z); a.w = scale*(1.0f + sr*rel.w);
    float4 c = make_float4(0.f,0.f,0.f,0.f);
    if (t >= 149){
      float srp = g_sreso[t-149];
      float4 hm = reinterpret_cast<const float4*>(g_hmean)[(t-149)*25 + tid];
      c.x = 0.4f*(1.0f + srp*rel.x)*hm.x;
      c.y = 0.4f*(1.0f + srp*rel.y)*hm.y;
      c.z = 0.4f*(1.0f + srp*rel.z)*hm.z;
      c.w = 0.4f*(1.0f + srp*rel.w)*hm.w;
    }
    s_a[tid] = a; s_c[tid] = c;
  }
  __syncthreads();
  // 32 rows x 25 packed-uint2 per t
  for (int q = tid; q < 800; q += 256){
    int row = q / 25;
    int kq  = q - row*25;
    size_t half_off = ((size_t)row*TT + t)*NH;
    uint2 pk = reinterpret_cast<const uint2*>(g_hmid + half_off)[kq];
    __half2 p0 = *reinterpret_cast<__half2*>(&pk.x);
    __half2 p1 = *reinterpret_cast<__half2*>(&pk.y);
    float2 v01 = __half22float2(p0);
    float2 v23 = __half22float2(p1);
    float4 a = s_a[kq], c = s_c[kq];
    float4 o;
    o.x = fmaf(a.x, v01.x, c.x); o.y = fmaf(a.y, v01.y, c.y);
    o.z = fmaf(a.z, v23.x, c.z); o.w = fmaf(a.w, v23.y, c.w);
    size_t idx = ((size_t)row*TT + t)*25 + kq;
    outh[idx] = o;
  }
}

extern "C" void kernel_launch(void* const* d_in, const int* in_sizes, int n_in,
                              void* d_out, int out_size){
  const float* harm  = (const float*)d_in[0];
  const float* noise = (const float*)d_in[1];
  float* outh = (float*)d_out;
  float* outn = outh + (size_t)BB*TT*NH;
  k_stats<<<TT, 512>>>(harm);
  k_scan <<<1, 256>>>();
  k_out  <<<TT + 2048, 256>>>((const float4*)noise, (float4*)outh, (float4*)outn);
}

// round 12
// speedup vs baseline: 1.3437x; 1.1381x over previous
#include <cuda_runtime.h>
#include <cuda_fp16.h>
#include <math.h>

#define TT 4096
#define BB 32
#define NH 100
#define NM 65

// ---- scratch (__device__ globals: allocations forbidden) ----
__device__ __align__(16) float  g_nfac[TT*NM];
__device__ __align__(16) __half g_hmid[(size_t)BB*TT*NH];   // 26.2MB fp16
__device__ __align__(16) float  g_hmean[TT*NH];
__device__ float g_cmean[TT];
__device__ float g_sreso[TT];

__device__ __forceinline__ float wmax(float v){
  #pragma unroll
  for (int d=16; d; d>>=1) v = fmaxf(v, __shfl_xor_sync(0xffffffffu, v, d));
  return v;
}
__device__ __forceinline__ float wsum(float v){
  #pragma unroll
  for (int d=16; d; d>>=1) v += __shfl_xor_sync(0xffffffffu, v, d);
  return v;
}

// ---- K1: per-t block: factors in-block, stats, fp16 h_mid store -----------
// 16 warps x 2 rows; cross-warp reduction via smem partials (NO atomics)
__global__ __launch_bounds__(512) void k_stats(const float* __restrict__ harm){
  int t = blockIdx.x;
  int warp = threadIdx.x>>5, lane = threadIdx.x&31;
  __shared__ float s_tfac[NH];
  __shared__ float s_part[16*104];     // per-warp 100-float partials, padded
  __shared__ float s_c[16];
  int tid = threadIdx.x;
  if (tid < NH+NM){
    // f32 phase recurrence tracked by double closed form (~1e-5 rad / 4096)
    const double INC  = (double)(float)1.0053096491487339;  // f32(2pi*40*64/16000)
    const double WRAP = (double)(float)6.283185307179586;   // f32(2pi)
    float phase = (float)fmod((double)(t+1)*INC, WRAP);
    if (tid < NH){
      float off = (float)((double)tid * (4.71238898038469/99.0));
      s_tfac[tid] = 1.0f + 0.225f*sinf(phase + off);
    } else {
      int m = tid - NH;
      float rb = (float)m * 7.853981633974483f;             // arange*2.5pi (f32)
      g_nfac[t*NM+m] = 1.0f + 0.6f*sinf(rb + phase);
    }
  }
  __syncthreads();
  bool act = lane < 25;
  float4 f = act ? reinterpret_cast<const float4*>(s_tfac)[lane]
                 : make_float4(0.f,0.f,0.f,0.f);
  float4 acc = make_float4(0.f,0.f,0.f,0.f);
  float cacc = 0.f;
  float k0 = (float)(lane*4);
  #pragma unroll
  for (int r=0;r<2;++r){
    int b = warp + r*16;
    size_t rowoff = ((size_t)b*TT + t)*NH;
    float4 x = act ? reinterpret_cast<const float4*>(harm + rowoff)[lane]
                   : make_float4(0.f,0.f,0.f,0.f);
    // single max tree: max(sharp) == max_orig^3.4 (monotone), ref clamps kept
    float mo = fmaxf(fmaxf(x.x,x.y), fmaxf(x.z,x.w));
    mo = fmaxf(wmax(mo), 1e-6f);
    float ms = fmaxf(__powf(mo, 3.4f), 1e-6f);
    float ratio = __fdividef(mo, ms);
    float4 s;
    s.x = __powf(fmaxf(x.x,1e-6f), 3.4f);
    s.y = __powf(fmaxf(x.y,1e-6f), 3.4f);
    s.z = __powf(fmaxf(x.z,1e-6f), 3.4f);
    s.w = __powf(fmaxf(x.w,1e-6f), 3.4f);
    float4 h;
    h.x = s.x*ratio*f.x; h.y = s.y*ratio*f.y;
    h.z = s.z*ratio*f.z; h.w = s.w*ratio*f.w;
    if (!act){ h.x=h.y=h.z=h.w=0.f; }
    float num = h.x*k0 + h.y*(k0+1.f) + h.z*(k0+2.f) + h.w*(k0+3.f);
    float den = h.x+h.y+h.z+h.w;
    num = wsum(num); den = wsum(den);
    if (lane==0) cacc += __fdividef(num, fmaxf(den, 1e-6f));
    if (act){
      __half2 p0 = __floats2half2_rn(h.x, h.y);
      __half2 p1 = __floats2half2_rn(h.z, h.w);
      uint2 pk;
      pk.x = *reinterpret_cast<unsigned int*>(&p0);
      pk.y = *reinterpret_cast<unsigned int*>(&p1);
      reinterpret_cast<uint2*>(g_hmid + rowoff)[lane] = pk;
    }
    acc.x+=h.x; acc.y+=h.y; acc.z+=h.z; acc.w+=h.w;
  }
  // per-warp partial -> smem (no atomics)
  if (act) reinterpret_cast<float4*>(&s_part[warp*104])[lane] = acc;
  if (lane==0) s_c[warp] = cacc;
  __syncthreads();
  if (tid < NH){
    float sum = 0.f;
    #pragma unroll
    for (int w=0; w<16; ++w) sum += s_part[w*104 + tid];
    g_hmean[t*NH+tid] = sum * (1.f/32.f);
  }
  if (tid == 0){
    float cs = 0.f;
    #pragma unroll
    for (int w=0; w<16; ++w) cs += s_c[w];
    g_cmean[t] = cs * (1.f/32.f);
  }
}

// ---- K2: fb affine scan + clock prefix sum (256 thr x 16 elems, double) ---
__global__ void k_scan(){
  __shared__ double s_clk[TT];
  __shared__ double s_wa[8], s_wb[8], s_ws[8];
  int tid = threadIdx.x;
  int lane = tid & 31, warp = tid >> 5;
  int base = tid * 16;
  const double RATE_K = 0.725 * 6.283185307179586 * 0.004;
  double v = 0.0;
  #pragma unroll
  for (int j=0;j<16;++j){
    double u = 0.1*(((double)g_cmean[base+j] - 30.0)/40.0);
    v = 0.9*v + u;
  }
  double a = 0.18530201888518416;  // 0.9^16
  double b = v;
  #pragma unroll
  for (int d=1; d<32; d<<=1){
    double pa = __shfl_up_sync(0xffffffffu, a, d);
    double pb = __shfl_up_sync(0xffffffffu, b, d);
    if (lane >= d){ b = a*pb + b; a = a*pa; }
  }
  if (lane == 31){ s_wa[warp]=a; s_wb[warp]=b; }
  __syncthreads();
  double wpre = 0.0;
  for (int w=0; w<warp; ++w) wpre = s_wa[w]*wpre + s_wb[w];
  double ae = __shfl_up_sync(0xffffffffu, a, 1);
  double be = __shfl_up_sync(0xffffffffu, b, 1);
  double fb = (lane==0) ? wpre : (ae*wpre + be);
  double csum = 0.0;
  #pragma unroll
  for (int j=0;j<16;++j){
    double u = 0.1*(((double)g_cmean[base+j] - 30.0)/40.0);
    fb = 0.9*fb + u;
    csum += RATE_K * (1.0 + 0.4*fb);
    s_clk[base+j] = csum;
  }
  double S = csum, ss = S;
  #pragma unroll
  for (int d=1; d<32; d<<=1){
    double p = __shfl_up_sync(0xffffffffu, ss, d);
    if (lane >= d) ss += p;
  }
  if (lane == 31) s_ws[warp] = ss;
  __syncthreads();
  double off = 0.0;
  for (int w=0; w<warp; ++w) off += s_ws[w];
  double excl = off + ss - S;
  #pragma unroll
  for (int j=0;j<16;++j){
    double c = fmod(excl + s_clk[base+j], 6.283185307179586);
    g_sreso[base+j] = 0.4f * sinf((float)c);
  }
}

// ---- K3: h epilogue (blocks [0,TT)) + noise stream (blocks >= TT) ---------
__global__ __launch_bounds__(256) void k_out(const float4* __restrict__ nin,
                                             float4* __restrict__ outh,
                                             float4* __restrict__ outn){
  int bid = blockIdx.x;
  int tid = threadIdx.x;
  if (bid >= TT){
    const int NVN = BB*TT*NM/4;
    int idx = (bid - TT)*256 + tid;
    int stride = (gridDim.x - TT)*256;
    for (int j = idx; j < NVN; j += stride){
      int fi = j % (TT*NM/4);
      float4 v = nin[j];
      float4 f = reinterpret_cast<const float4*>(g_nfac)[fi];
      v.x *= f.x; v.y *= f.y; v.z *= f.z; v.w *= f.w;
      outn[j] = v;
    }
    return;
  }
  int t = bid;
  __shared__ float4 s_a[25], s_c[25];
  if (tid < 25){
    float sr = g_sreso[t];
    int k4 = tid*4;
    float4 rel;
    rel.x = (float)k4/99.0f*2.0f - 1.0f;
    rel.y = (float)(k4+1)/99.0f*2.0f - 1.0f;
    rel.z = (float)(k4+2)/99.0f*2.0f - 1.0f;
    rel.w = (float)(k4+3)/99.0f*2.0f - 1.0f;
    float scale = (t==0) ? 1.0f : 0.6f;
    float4 a;
    a.x = scale*(1.0f + sr*rel.x); a.y = scale*(1.0f + sr*rel.y);
    a.z = scale*(1.0f + sr*rel.z); a.w = scale*(1.0f + sr*rel.w);
    float4 c = make_float4(0.f,0.f,0.f,0.f);
    if (t >= 149){
      float srp = g_sreso[t-149];
      float4 hm = reinterpret_cast<const float4*>(g_hmean)[(t-149)*25 + tid];
      c.x = 0.4f*(1.0f + srp*rel.x)*hm.x;
      c.y = 0.4f*(1.0f + srp*rel.y)*hm.y;
      c.z = 0.4f*(1.0f + srp*rel.z)*hm.z;
      c.w = 0.4f*(1.0f + srp*rel.w)*hm.w;
    }
    s_a[tid] = a; s_c[tid] = c;
  }
  __syncthreads();
  // 32 rows x 25 packed-uint2 per t
  for (int q = tid; q < 800; q += 256){
    int row = q / 25;
    int kq  = q - row*25;
    size_t half_off = ((size_t)row*TT + t)*NH;
    uint2 pk = reinterpret_cast<const uint2*>(g_hmid + half_off)[kq];
    __half2 p0 = *reinterpret_cast<__half2*>(&pk.x);
    __half2 p1 = *reinterpret_cast<__half2*>(&pk.y);
    float2 v01 = __half22float2(p0);
    float2 v23 = __half22float2(p1);
    float4 a = s_a[kq], c = s_c[kq];
    float4 o;
    o.x = fmaf(a.x, v01.x, c.x); o.y = fmaf(a.y, v01.y, c.y);
    o.z = fmaf(a.z, v23.x, c.z); o.w = fmaf(a.w, v23.y, c.w);
    size_t idx = ((size_t)row*TT + t)*25 + kq;
    outh[idx] = o;
  }
}

extern "C" void kernel_launch(void* const* d_in, const int* in_sizes, int n_in,
                              void* d_out, int out_size){
  const float* harm  = (const float*)d_in[0];
  const float* noise = (const float*)d_in[1];
  float* outh = (float*)d_out;
  float* outn = outh + (size_t)BB*TT*NH;
  k_stats<<<TT, 512>>>(harm);
  k_scan <<<1, 256>>>();
  k_out  <<<TT + 2048, 256>>>((const float4*)noise, (float4*)outh, (float4*)outn);
}

// round 13
// speedup vs baseline: 1.4498x; 1.0790x over previous
#include <cuda_runtime.h>
#include <cuda_fp16.h>
#include <math.h>

#define TT 4096
#define BB 32
#define NH 100
#define NM 65
#define PADK 104
#define PADR 27

// ---- scratch (__device__ globals: allocations forbidden) ----
__device__ __align__(16) float  g_nfac[TT*NM];
__device__ __align__(16) __half g_hmid[(size_t)BB*TT*NH];   // 26.2MB fp16 (stores sf, ratio deferred)
__device__ __align__(16) float  g_hmean[TT*NH];
__device__ float g_ratio[TT*BB];          // ratio[t][b]
__device__ float g_cmean[TT];
__device__ float g_sreso[TT];

__device__ __forceinline__ float wsum(float v){
  #pragma unroll
  for (int d=16; d; d>>=1) v += __shfl_xor_sync(0xffffffffu, v, d);
  return v;
}

// ---- K1: per-t block. Phase1: pow+partials (no shuffles). Phase2: reduce. --
__global__ __launch_bounds__(512) void k_stats(const float* __restrict__ harm){
  int t = blockIdx.x;
  int warp = threadIdx.x>>5, lane = threadIdx.x&31;
  int tid = threadIdx.x;
  __shared__ float s_tfac[NH];
  __shared__ float s_sf[32*PADK];     // fp32 sf per row (13.3KB)
  __shared__ float s_max[32*PADR];
  __shared__ float s_num[32*PADR];
  __shared__ float s_den[32*PADR];
  __shared__ float s_r[32];
  if (tid < NH+NM){
    // f32 phase recurrence tracked by double closed form (~1e-5 rad / 4096)
    const double INC  = (double)(float)1.0053096491487339;  // f32(2pi*40*64/16000)
    const double WRAP = (double)(float)6.283185307179586;   // f32(2pi)
    float phase = (float)fmod((double)(t+1)*INC, WRAP);
    if (tid < NH){
      float off = (float)((double)tid * (4.71238898038469/99.0));
      s_tfac[tid] = 1.0f + 0.225f*sinf(phase + off);
    } else {
      int m = tid - NH;
      float rb = (float)m * 7.853981633974483f;             // arange*2.5pi (f32)
      g_nfac[t*NM+m] = 1.0f + 0.6f*sinf(rb + phase);
    }
  }
  __syncthreads();
  bool act = lane < 25;
  float4 f = act ? reinterpret_cast<const float4*>(s_tfac)[lane]
                 : make_float4(0.f,0.f,0.f,0.f);
  float k0 = (float)(lane*4);
  #pragma unroll
  for (int r=0;r<2;++r){
    int b = warp + r*16;                      // row 0..31
    size_t rowoff = ((size_t)b*TT + t)*NH;
    float4 x = act ? reinterpret_cast<const float4*>(harm + rowoff)[lane]
                   : make_float4(0.f,0.f,0.f,0.f);
    // pow without clamp: x>=0; x<1e-6 diff <= 9e-21 abs (negligible)
    float4 sf;
    sf.x = __powf(x.x, 3.4f)*f.x;
    sf.y = __powf(x.y, 3.4f)*f.y;
    sf.z = __powf(x.z, 3.4f)*f.z;
    sf.w = __powf(x.w, 3.4f)*f.w;
    float lmax = fmaxf(fmaxf(x.x,x.y), fmaxf(x.z,x.w));
    float num = sf.x*k0 + sf.y*(k0+1.f) + sf.z*(k0+2.f) + sf.w*(k0+3.f);
    float den = sf.x+sf.y+sf.z+sf.w;
    if (act){
      reinterpret_cast<float4*>(s_sf + b*PADK)[lane] = sf;
      s_max[b*PADR+lane] = lmax;
      s_num[b*PADR+lane] = num;
      s_den[b*PADR+lane] = den;
      __half2 p0 = __floats2half2_rn(sf.x, sf.y);
      __half2 p1 = __floats2half2_rn(sf.z, sf.w);
      uint2 pk;
      pk.x = *reinterpret_cast<unsigned int*>(&p0);
      pk.y = *reinterpret_cast<unsigned int*>(&p1);
      reinterpret_cast<uint2*>(g_hmid + rowoff)[lane] = pk;
    }
  }
  __syncthreads();
  // Phase 2a: warp 0, one thread per row
  if (tid < 32){
    int row = tid;
    float mo = 0.f, num = 0.f, den = 0.f;
    #pragma unroll
    for (int l=0;l<25;++l){
      mo  = fmaxf(mo, s_max[row*PADR+l]);
      num += s_num[row*PADR+l];
      den += s_den[row*PADR+l];
    }
    mo = fmaxf(mo, 1e-6f);
    float ms = fmaxf(__powf(mo, 3.4f), 1e-6f);
    float ratio = __fdividef(mo, ms);
    // ratio cancels in num/den (clamp at 1e-6 practically never binds)
    float cen = __fdividef(num, fmaxf(den, 1e-6f));
    s_r[row] = ratio;
    g_ratio[t*32+row] = ratio;
    float cs = wsum(cen);
    if (row == 0) g_cmean[t] = cs * (1.f/32.f);
  }
  __syncthreads();
  // Phase 2b: hmean[k] = sum_b ratio_b * sf[b][k] / 32
  if (tid < NH){
    float sum = 0.f;
    #pragma unroll
    for (int b=0;b<32;++b) sum = fmaf(s_r[b], s_sf[b*PADK+tid], sum);
    g_hmean[t*NH+tid] = sum * (1.f/32.f);
  }
}

// ---- K2: fb affine scan + clock prefix sum (256 thr x 16 elems, double) ---
__global__ void k_scan(){
  __shared__ double s_clk[TT];
  __shared__ double s_wa[8], s_wb[8], s_ws[8];
  int tid = threadIdx.x;
  int lane = tid & 31, warp = tid >> 5;
  int base = tid * 16;
  const double RATE_K = 0.725 * 6.283185307179586 * 0.004;
  double v = 0.0;
  #pragma unroll
  for (int j=0;j<16;++j){
    double u = 0.1*(((double)g_cmean[base+j] - 30.0)/40.0);
    v = 0.9*v + u;
  }
  double a = 0.18530201888518416;  // 0.9^16
  double b = v;
  #pragma unroll
  for (int d=1; d<32; d<<=1){
    double pa = __shfl_up_sync(0xffffffffu, a, d);
    double pb = __shfl_up_sync(0xffffffffu, b, d);
    if (lane >= d){ b = a*pb + b; a = a*pa; }
  }
  if (lane == 31){ s_wa[warp]=a; s_wb[warp]=b; }
  __syncthreads();
  double wpre = 0.0;
  for (int w=0; w<warp; ++w) wpre = s_wa[w]*wpre + s_wb[w];
  double ae = __shfl_up_sync(0xffffffffu, a, 1);
  double be = __shfl_up_sync(0xffffffffu, b, 1);
  double fb = (lane==0) ? wpre : (ae*wpre + be);
  double csum = 0.0;
  #pragma unroll
  for (int j=0;j<16;++j){
    double u = 0.1*(((double)g_cmean[base+j] - 30.0)/40.0);
    fb = 0.9*fb + u;
    csum += RATE_K * (1.0 + 0.4*fb);
    s_clk[base+j] = csum;
  }
  double S = csum, ss = S;
  #pragma unroll
  for (int d=1; d<32; d<<=1){
    double p = __shfl_up_sync(0xffffffffu, ss, d);
    if (lane >= d) ss += p;
  }
  if (lane == 31) s_ws[warp] = ss;
  __syncthreads();
  double off = 0.0;
  for (int w=0; w<warp; ++w) off += s_ws[w];
  double excl = off + ss - S;
  #pragma unroll
  for (int j=0;j<16;++j){
    double c = fmod(excl + s_clk[base+j], 6.283185307179586);
    g_sreso[base+j] = 0.4f * sinf((float)c);
  }
}

// ---- K3: h epilogue (blocks [0,TT)) + noise stream (blocks >= TT) ---------
__global__ __launch_bounds__(256) void k_out(const float4* __restrict__ nin,
                                             float4* __restrict__ outh,
                                             float4* __restrict__ outn){
  int bid = blockIdx.x;
  int tid = threadIdx.x;
  if (bid >= TT){
    const int NVN = BB*TT*NM/4;
    int idx = (bid - TT)*256 + tid;
    int stride = (gridDim.x - TT)*256;
    for (int j = idx; j < NVN; j += stride){
      int fi = j % (TT*NM/4);
      float4 v = nin[j];
      float4 f = reinterpret_cast<const float4*>(g_nfac)[fi];
      v.x *= f.x; v.y *= f.y; v.z *= f.z; v.w *= f.w;
      outn[j] = v;
    }
    return;
  }
  int t = bid;
  __shared__ float4 s_a[25], s_c[25];
  __shared__ float  s_r2[32];
  if (tid < 32) s_r2[tid] = g_ratio[t*32+tid];
  if (tid < 25){
    float sr = g_sreso[t];
    int k4 = tid*4;
    float4 rel;
    rel.x = (float)k4/99.0f*2.0f - 1.0f;
    rel.y = (float)(k4+1)/99.0f*2.0f - 1.0f;
    rel.z = (float)(k4+2)/99.0f*2.0f - 1.0f;
    rel.w = (float)(k4+3)/99.0f*2.0f - 1.0f;
    float scale = (t==0) ? 1.0f : 0.6f;
    float4 a;
    a.x = scale*(1.0f + sr*rel.x); a.y = scale*(1.0f + sr*rel.y);
    a.z = scale*(1.0f + sr*rel.z); a.w = scale*(1.0f + sr*rel.w);
    float4 c = make_float4(0.f,0.f,0.f,0.f);
    if (t >= 149){
      float srp = g_sreso[t-149];
      float4 hm = reinterpret_cast<const float4*>(g_hmean)[(t-149)*25 + tid];
      c.x = 0.4f*(1.0f + srp*rel.x)*hm.x;
      c.y = 0.4f*(1.0f + srp*rel.y)*hm.y;
      c.z = 0.4f*(1.0f + srp*rel.z)*hm.z;
      c.w = 0.4f*(1.0f + srp*rel.w)*hm.w;
    }
    s_a[tid] = a; s_c[tid] = c;
  }
  __syncthreads();
  for (int q = tid; q < 800; q += 256){
    int row = q / 25;
    int kq  = q - row*25;
    float r = s_r2[row];
    size_t half_off = ((size_t)row*TT + t)*NH;
    uint2 pk = reinterpret_cast<const uint2*>(g_hmid + half_off)[kq];
    __half2 p0 = *reinterpret_cast<__half2*>(&pk.x);
    __half2 p1 = *reinterpret_cast<__half2*>(&pk.y);
    float2 v01 = __half22float2(p0);
    float2 v23 = __half22float2(p1);
    float4 a = s_a[kq], c = s_c[kq];
    float4 o;
    o.x = fmaf(a.x, r*v01.x, c.x); o.y = fmaf(a.y, r*v01.y, c.y);
    o.z = fmaf(a.z, r*v23.x, c.z); o.w = fmaf(a.w, r*v23.y, c.w);
    size_t idx = ((size_t)row*TT + t)*25 + kq;
    outh[idx] = o;
  }
}

extern "C" void kernel_launch(void* const* d_in, const int* in_sizes, int n_in,
                              void* d_out, int out_size){
  const float* harm  = (const float*)d_in[0];
  const float* noise = (const float*)d_in[1];
  float* outh = (float*)d_out;
  float* outn = outh + (size_t)BB*TT*NH;
  k_stats<<<TT, 512>>>(harm);
  k_scan <<<1, 256>>>();
  k_out  <<<TT + 2048, 256>>>((const float4*)noise, (float4*)outh, (float4*)outn);
}